// round 1
// baseline (speedup 1.0000x reference)
#include <cuda_runtime.h>
#include <cstdint>

// Tree-RNN: leaf embed GEMM -> 13 combine GEMMs (pair concat == reinterpret
// [n,512] as [n/2,1024]) -> root projection.
//
// Scratch (no cudaMalloc allowed): ping-pong device globals.
__device__ float g_bufA[8192 * 512];        // 16 MB
__device__ float g_bufB[4096 * 512];        //  8 MB

// ---------------------------------------------------------------------------
// C[m,n] = act( sum_k A[m,k] * W[n,k] + bias[n] )
// A: [M,K] row-major, W: [N,K] row-major (i.e. computes A @ W^T).
// Block tile 128x128, K-tile 16, 256 threads, 8x8 per-thread register tile.
// N and K must be multiples of 128/16 respectively (true here: N=512,
// K in {4096,1024}); M is bounds-checked (combine levels shrink below 128).
// ---------------------------------------------------------------------------
template <bool RELU>
__global__ __launch_bounds__(256, 2)
void sgemm_bias_act(const float* __restrict__ A,
                    const float* __restrict__ W,
                    const float* __restrict__ bias,
                    float* __restrict__ C,
                    int M, int N, int K)
{
    constexpr int BM = 128, BN = 128, BK = 16, TM = 8, TN = 8;

    __shared__ float As[BK][BM];   // transposed stage: As[k][m]
    __shared__ float Bs[BK][BN];   // Bs[k][n] = W[n][k]

    const int tid = threadIdx.x;                 // 0..255
    const int bm  = blockIdx.y * BM;
    const int bn  = blockIdx.x * BN;

    // Global-load assignments: 128 rows x 16 cols = 2048 floats = 8/thread
    // (two float4 per thread: rows tid/4 and tid/4 + 64).
    const int ldRow = tid >> 2;                  // 0..63
    const int ldCol = (tid & 3) * 4;             // 0,4,8,12

    // Compute assignment: 16x16 thread grid, each owns 8x8 outputs.
    const int tRow = (tid >> 4) * TM;            // 0..120
    const int tCol = (tid & 15) * TN;            // 0..120

    float acc[TM][TN];
    #pragma unroll
    for (int i = 0; i < TM; i++)
        #pragma unroll
        for (int j = 0; j < TN; j++) acc[i][j] = 0.0f;

    for (int k0 = 0; k0 < K; k0 += BK) {
        // --- stage A tile (two halves of 64 rows) ---
        #pragma unroll
        for (int h = 0; h < 2; h++) {
            const int r = ldRow + h * 64;
            float4 a4;
            if (bm + r < M)
                a4 = *reinterpret_cast<const float4*>(
                         A + (size_t)(bm + r) * K + k0 + ldCol);
            else
                a4 = make_float4(0.f, 0.f, 0.f, 0.f);
            As[ldCol + 0][r] = a4.x;
            As[ldCol + 1][r] = a4.y;
            As[ldCol + 2][r] = a4.z;
            As[ldCol + 3][r] = a4.w;
        }
        // --- stage W tile (N=512 is always in-bounds) ---
        #pragma unroll
        for (int h = 0; h < 2; h++) {
            const int r = ldRow + h * 64;        // n index within tile
            float4 w4 = *reinterpret_cast<const float4*>(
                            W + (size_t)(bn + r) * K + k0 + ldCol);
            Bs[ldCol + 0][r] = w4.x;
            Bs[ldCol + 1][r] = w4.y;
            Bs[ldCol + 2][r] = w4.z;
            Bs[ldCol + 3][r] = w4.w;
        }
        __syncthreads();

        #pragma unroll
        for (int kk = 0; kk < BK; kk++) {
            float ra[TM], rb[TN];
            // vector LDS: tRow/tCol are 8-aligned -> float4 pairs
            *reinterpret_cast<float4*>(&ra[0]) =
                *reinterpret_cast<const float4*>(&As[kk][tRow]);
            *reinterpret_cast<float4*>(&ra[4]) =
                *reinterpret_cast<const float4*>(&As[kk][tRow + 4]);
            *reinterpret_cast<float4*>(&rb[0]) =
                *reinterpret_cast<const float4*>(&Bs[kk][tCol]);
            *reinterpret_cast<float4*>(&rb[4]) =
                *reinterpret_cast<const float4*>(&Bs[kk][tCol + 4]);
            #pragma unroll
            for (int i = 0; i < TM; i++)
                #pragma unroll
                for (int j = 0; j < TN; j++)
                    acc[i][j] = fmaf(ra[i], rb[j], acc[i][j]);
        }
        __syncthreads();
    }

    // --- epilogue: bias + activation, vectorized float4 stores ---
    float bv[TN];
    #pragma unroll
    for (int j = 0; j < TN; j++) bv[j] = bias[bn + tCol + j];

    #pragma unroll
    for (int i = 0; i < TM; i++) {
        const int m = bm + tRow + i;
        if (m >= M) break;
        float v[TN];
        #pragma unroll
        for (int j = 0; j < TN; j++) {
            float x = acc[i][j] + bv[j];
            v[j] = (RELU && x < 0.f) ? 0.f : x;
        }
        float* dst = C + (size_t)m * N + bn + tCol;
        *reinterpret_cast<float4*>(dst)     = *reinterpret_cast<float4*>(&v[0]);
        *reinterpret_cast<float4*>(dst + 4) = *reinterpret_cast<float4*>(&v[4]);
    }
}

// Root projection: out[c] = sum_k h[k] * Wp[c*512+k] + bp[c], c in {0,1}
__global__ void proj_kernel(const float* __restrict__ h,
                            const float* __restrict__ Wp,
                            const float* __restrict__ bp,
                            float* __restrict__ out)
{
    const int w    = threadIdx.x >> 5;   // warp 0 -> class 0, warp 1 -> class 1
    const int lane = threadIdx.x & 31;
    float s = 0.f;
    for (int k = lane; k < 512; k += 32)
        s = fmaf(h[k], Wp[w * 512 + k], s);
    #pragma unroll
    for (int o = 16; o > 0; o >>= 1)
        s += __shfl_xor_sync(0xffffffffu, s, o);
    if (lane == 0) out[w] = s + bp[w];
}

extern "C" void kernel_launch(void* const* d_in, const int* in_sizes, int n_in,
                              void* d_out, int out_size)
{
    const float* leaf  = (const float*)d_in[0];   // [8192, 4096]
    const float* Wemb  = (const float*)d_in[1];   // [512, 4096]
    const float* bemb  = (const float*)d_in[2];   // [512]
    const float* Wcomb = (const float*)d_in[3];   // [512, 1024]
    const float* bcomb = (const float*)d_in[4];   // [512]
    const float* Wproj = (const float*)d_in[5];   // [2, 512]
    const float* bproj = (const float*)d_in[6];   // [2]
    float* out = (float*)d_out;                   // [1, 2]

    float *bufA = nullptr, *bufB = nullptr;
    cudaGetSymbolAddress((void**)&bufA, g_bufA);
    cudaGetSymbolAddress((void**)&bufB, g_bufB);

    // Leaf embedding: [8192,4096] @ [512,4096]^T -> bufA [8192,512]
    {
        dim3 grid(512 / 128, 8192 / 128);
        sgemm_bias_act<true><<<grid, 256>>>(leaf, Wemb, bemb, bufA,
                                            8192, 512, 4096);
    }

    // 13 combine levels. Input [rows,512] viewed as [rows/2,1024].
    float* cur = bufA;
    float* nxt = bufB;
    int rows = 8192;
    while (rows > 1) {
        const int m = rows / 2;
        dim3 grid(512 / 128, (m + 127) / 128);
        sgemm_bias_act<true><<<grid, 256>>>(cur, Wcomb, bcomb, nxt,
                                            m, 512, 1024);
        float* t = cur; cur = nxt; nxt = t;
        rows = m;
    }

    // Root projection -> [1,2]
    proj_kernel<<<1, 64>>>(cur, Wproj, bproj, out);
}

// round 2
// speedup vs baseline: 3.1301x; 3.1301x over previous
#include <cuda_runtime.h>
#include <cuda_bf16.h>
#include <cstdint>

// Tree-RNN on tensor cores.
// All GEMMs computed as C = A @ W^T with fp32 I/O but bf16x3-split
// mma.sync.m16n8k16 (a_hi*b_hi + a_hi*b_lo + a_lo*b_hi, fp32 accum).
// Error of dropped a_lo*b_lo term ~2^-16 relative -> final rel_err ~1e-5.

__device__ float g_bufA[8192 * 512];   // 16 MB ping
__device__ float g_bufB[4096 * 512];   //  8 MB pong

#define BM 128
#define BN 64
#define BK 64
#define LDA 72              // BK + 8 pad (bf16 units) -> conflict-free frags
#define SMEM_BYTES ((2 * BM * LDA + 2 * BN * LDA) * 2)   // 55296

__device__ __forceinline__ void mma_bf16(float c[4], const uint32_t a[4],
                                         const uint32_t b[2]) {
    asm volatile(
        "mma.sync.aligned.m16n8k16.row.col.f32.bf16.bf16.f32 "
        "{%0,%1,%2,%3}, {%4,%5,%6,%7}, {%8,%9}, {%0,%1,%2,%3};\n"
        : "+f"(c[0]), "+f"(c[1]), "+f"(c[2]), "+f"(c[3])
        : "r"(a[0]), "r"(a[1]), "r"(a[2]), "r"(a[3]), "r"(b[0]), "r"(b[1]));
}

// C[m,n] = relu( sum_k A[m,k]*W[n,k] + bias[n] ), A:[M,K], W:[N,K] row-major.
// K % 64 == 0, N % 64 == 0. M bounds-checked.
template <bool RELU>
__global__ __launch_bounds__(256, 2)
void gemm3_bf16(const float* __restrict__ A, const float* __restrict__ W,
                const float* __restrict__ bias, float* __restrict__ C,
                int M, int N, int K)
{
    extern __shared__ __nv_bfloat16 smem[];
    __nv_bfloat16* As_h = smem;
    __nv_bfloat16* As_l = As_h + BM * LDA;
    __nv_bfloat16* Bs_h = As_l + BM * LDA;
    __nv_bfloat16* Bs_l = Bs_h + BN * LDA;

    const int tid  = threadIdx.x;
    const int lane = tid & 31;
    const int wid  = tid >> 5;            // 0..7
    const int wm   = (wid & 3) * 32;      // warp M offset in tile
    const int wn   = (wid >> 2) * 32;     // warp N offset in tile

    const int bm = blockIdx.y * BM;
    const int bn = blockIdx.x * BN;

    float acc[2][4][4];
    #pragma unroll
    for (int i = 0; i < 2; i++)
        #pragma unroll
        for (int j = 0; j < 4; j++)
            #pragma unroll
            for (int v = 0; v < 4; v++) acc[i][j][v] = 0.f;

    // staging: each thread handles float4 chunks; 16 float4 per 64-wide row
    const int srow = tid >> 4;            // 0..15
    const int scol = (tid & 15) * 4;      // fp32 col 0..60

    const int lq = (lane & 3) * 2;        // k sub-offset within frag
    const int lr = lane >> 2;             // row sub-offset within frag

    for (int k0 = 0; k0 < K; k0 += BK) {
        // ---- stage A (128 rows): 8 chunks/thread ----
        #pragma unroll
        for (int i = 0; i < 8; i++) {
            const int r = srow + i * 16;
            float4 v;
            if (bm + r < M)
                v = *reinterpret_cast<const float4*>(A + (size_t)(bm + r) * K + k0 + scol);
            else
                v = make_float4(0.f, 0.f, 0.f, 0.f);
            __nv_bfloat16 h0 = __float2bfloat16(v.x), h1 = __float2bfloat16(v.y);
            __nv_bfloat16 h2 = __float2bfloat16(v.z), h3 = __float2bfloat16(v.w);
            __nv_bfloat162 hh0 = {h0, h1}, hh1 = {h2, h3};
            __nv_bfloat162 ll0 = {__float2bfloat16(v.x - __bfloat162float(h0)),
                                  __float2bfloat16(v.y - __bfloat162float(h1))};
            __nv_bfloat162 ll1 = {__float2bfloat16(v.z - __bfloat162float(h2)),
                                  __float2bfloat16(v.w - __bfloat162float(h3))};
            *reinterpret_cast<__nv_bfloat162*>(&As_h[r * LDA + scol])     = hh0;
            *reinterpret_cast<__nv_bfloat162*>(&As_h[r * LDA + scol + 2]) = hh1;
            *reinterpret_cast<__nv_bfloat162*>(&As_l[r * LDA + scol])     = ll0;
            *reinterpret_cast<__nv_bfloat162*>(&As_l[r * LDA + scol + 2]) = ll1;
        }
        // ---- stage W (64 rows): 4 chunks/thread (N=512 always in-bounds) ----
        #pragma unroll
        for (int i = 0; i < 4; i++) {
            const int r = srow + i * 16;
            float4 v = *reinterpret_cast<const float4*>(W + (size_t)(bn + r) * K + k0 + scol);
            __nv_bfloat16 h0 = __float2bfloat16(v.x), h1 = __float2bfloat16(v.y);
            __nv_bfloat16 h2 = __float2bfloat16(v.z), h3 = __float2bfloat16(v.w);
            __nv_bfloat162 hh0 = {h0, h1}, hh1 = {h2, h3};
            __nv_bfloat162 ll0 = {__float2bfloat16(v.x - __bfloat162float(h0)),
                                  __float2bfloat16(v.y - __bfloat162float(h1))};
            __nv_bfloat162 ll1 = {__float2bfloat16(v.z - __bfloat162float(h2)),
                                  __float2bfloat16(v.w - __bfloat162float(h3))};
            *reinterpret_cast<__nv_bfloat162*>(&Bs_h[r * LDA + scol])     = hh0;
            *reinterpret_cast<__nv_bfloat162*>(&Bs_h[r * LDA + scol + 2]) = hh1;
            *reinterpret_cast<__nv_bfloat162*>(&Bs_l[r * LDA + scol])     = ll0;
            *reinterpret_cast<__nv_bfloat162*>(&Bs_l[r * LDA + scol + 2]) = ll1;
        }
        __syncthreads();

        #pragma unroll
        for (int ks = 0; ks < BK; ks += 16) {
            uint32_t ah[2][4], al[2][4], bh[4][2], bl[4][2];
            const int kq = ks + lq;
            #pragma unroll
            for (int mi = 0; mi < 2; mi++) {
                const int r0 = wm + mi * 16 + lr;
                ah[mi][0] = *reinterpret_cast<const uint32_t*>(&As_h[r0 * LDA + kq]);
                ah[mi][1] = *reinterpret_cast<const uint32_t*>(&As_h[(r0 + 8) * LDA + kq]);
                ah[mi][2] = *reinterpret_cast<const uint32_t*>(&As_h[r0 * LDA + kq + 8]);
                ah[mi][3] = *reinterpret_cast<const uint32_t*>(&As_h[(r0 + 8) * LDA + kq + 8]);
                al[mi][0] = *reinterpret_cast<const uint32_t*>(&As_l[r0 * LDA + kq]);
                al[mi][1] = *reinterpret_cast<const uint32_t*>(&As_l[(r0 + 8) * LDA + kq]);
                al[mi][2] = *reinterpret_cast<const uint32_t*>(&As_l[r0 * LDA + kq + 8]);
                al[mi][3] = *reinterpret_cast<const uint32_t*>(&As_l[(r0 + 8) * LDA + kq + 8]);
            }
            #pragma unroll
            for (int ni = 0; ni < 4; ni++) {
                const int c0 = wn + ni * 8 + lr;
                bh[ni][0] = *reinterpret_cast<const uint32_t*>(&Bs_h[c0 * LDA + kq]);
                bh[ni][1] = *reinterpret_cast<const uint32_t*>(&Bs_h[c0 * LDA + kq + 8]);
                bl[ni][0] = *reinterpret_cast<const uint32_t*>(&Bs_l[c0 * LDA + kq]);
                bl[ni][1] = *reinterpret_cast<const uint32_t*>(&Bs_l[c0 * LDA + kq + 8]);
            }
            #pragma unroll
            for (int mi = 0; mi < 2; mi++)
                #pragma unroll
                for (int ni = 0; ni < 4; ni++) {
                    mma_bf16(acc[mi][ni], ah[mi], bh[ni]);
                    mma_bf16(acc[mi][ni], ah[mi], bl[ni]);
                    mma_bf16(acc[mi][ni], al[mi], bh[ni]);
                }
        }
        __syncthreads();
    }

    // ---- epilogue: bias + relu, float2 stores ----
    #pragma unroll
    for (int mi = 0; mi < 2; mi++) {
        #pragma unroll
        for (int ni = 0; ni < 4; ni++) {
            const int m0 = bm + wm + mi * 16 + lr;
            const int n  = bn + wn + ni * 8 + lq;
            const float bv0 = bias[n], bv1 = bias[n + 1];
            if (m0 < M) {
                float x0 = acc[mi][ni][0] + bv0;
                float x1 = acc[mi][ni][1] + bv1;
                if (RELU) { x0 = fmaxf(x0, 0.f); x1 = fmaxf(x1, 0.f); }
                *reinterpret_cast<float2*>(C + (size_t)m0 * N + n) = make_float2(x0, x1);
            }
            if (m0 + 8 < M) {
                float x2 = acc[mi][ni][2] + bv0;
                float x3 = acc[mi][ni][3] + bv1;
                if (RELU) { x2 = fmaxf(x2, 0.f); x3 = fmaxf(x3, 0.f); }
                *reinterpret_cast<float2*>(C + (size_t)(m0 + 8) * N + n) = make_float2(x2, x3);
            }
        }
    }
}

// Root projection: out[c] = sum_k h[k]*Wp[c*512+k] + bp[c]
__global__ void proj_kernel(const float* __restrict__ h,
                            const float* __restrict__ Wp,
                            const float* __restrict__ bp,
                            float* __restrict__ out)
{
    const int w    = threadIdx.x >> 5;
    const int lane = threadIdx.x & 31;
    float s = 0.f;
    for (int k = lane; k < 512; k += 32)
        s = fmaf(h[k], Wp[w * 512 + k], s);
    #pragma unroll
    for (int o = 16; o > 0; o >>= 1)
        s += __shfl_xor_sync(0xffffffffu, s, o);
    if (lane == 0) out[w] = s + bp[w];
}

extern "C" void kernel_launch(void* const* d_in, const int* in_sizes, int n_in,
                              void* d_out, int out_size)
{
    const float* leaf  = (const float*)d_in[0];   // [8192, 4096]
    const float* Wemb  = (const float*)d_in[1];   // [512, 4096]
    const float* bemb  = (const float*)d_in[2];   // [512]
    const float* Wcomb = (const float*)d_in[3];   // [512, 1024]
    const float* bcomb = (const float*)d_in[4];   // [512]
    const float* Wproj = (const float*)d_in[5];   // [2, 512]
    const float* bproj = (const float*)d_in[6];   // [2]
    float* out = (float*)d_out;

    float *bufA = nullptr, *bufB = nullptr;
    cudaGetSymbolAddress((void**)&bufA, g_bufA);
    cudaGetSymbolAddress((void**)&bufB, g_bufB);

    cudaFuncSetAttribute(gemm3_bf16<true>,
                         cudaFuncAttributeMaxDynamicSharedMemorySize, SMEM_BYTES);

    // Leaf embedding: [8192,4096] @ [512,4096]^T -> bufA
    {
        dim3 grid(512 / BN, 8192 / BM);
        gemm3_bf16<true><<<grid, 256, SMEM_BYTES>>>(leaf, Wemb, bemb, bufA,
                                                    8192, 512, 4096);
    }

    // 13 combine levels; [rows,512] viewed as [rows/2,1024]
    float* cur = bufA;
    float* nxt = bufB;
    int rows = 8192;
    while (rows > 1) {
        const int m = rows / 2;
        dim3 grid(512 / BN, (m + BM - 1) / BM);
        gemm3_bf16<true><<<grid, 256, SMEM_BYTES>>>(cur, Wcomb, bcomb, nxt,
                                                    m, 512, 1024);
        float* t = cur; cur = nxt; nxt = t;
        rows = m;
    }

    proj_kernel<<<1, 64>>>(cur, Wproj, bproj, out);
}

// round 3
// speedup vs baseline: 3.2999x; 1.0542x over previous
#include <cuda_runtime.h>
#include <cuda_bf16.h>
#include <cstdint>

// Tree-RNN, bf16x3-split GEMMs on tensor cores with cp.async double buffering
// and ldmatrix fragment loads. All operands pre-split into bf16 (hi, lo);
// GEMM computes ah*bh + ah*bl + al*bh with fp32 accum, epilogue re-splits.

#define BM 128
#define BN 64
#define BK 64
#define LDA_B 144                       // smem row pitch in bytes (64 bf16 + 8 pad)
#define A_TILE_B (BM * LDA_B)           // 18432
#define B_TILE_B (BN * LDA_B)           // 9216
#define STAGE_B (2 * A_TILE_B + 2 * B_TILE_B)   // 55296
#define SMEM_TOTAL (2 * STAGE_B)                // 110592

// ---------------- device scratch (no allocation allowed) ----------------
__device__ __nv_bfloat16 g_leaf_hi[8192ull * 4096];
__device__ __nv_bfloat16 g_leaf_lo[8192ull * 4096];
__device__ __nv_bfloat16 g_We_hi[512 * 4096];
__device__ __nv_bfloat16 g_We_lo[512 * 4096];
__device__ __nv_bfloat16 g_Wc_hi[512 * 1024];
__device__ __nv_bfloat16 g_Wc_lo[512 * 1024];
__device__ __nv_bfloat16 g_hA[8192 * 512], g_lA[8192 * 512];
__device__ __nv_bfloat16 g_hB[4096 * 512], g_lB[4096 * 512];

// ---------------- PTX helpers ----------------
__device__ __forceinline__ void mma_bf16(float c[4], const uint32_t a[4],
                                         const uint32_t b0, const uint32_t b1) {
    asm volatile(
        "mma.sync.aligned.m16n8k16.row.col.f32.bf16.bf16.f32 "
        "{%0,%1,%2,%3}, {%4,%5,%6,%7}, {%8,%9}, {%0,%1,%2,%3};\n"
        : "+f"(c[0]), "+f"(c[1]), "+f"(c[2]), "+f"(c[3])
        : "r"(a[0]), "r"(a[1]), "r"(a[2]), "r"(a[3]), "r"(b0), "r"(b1));
}
__device__ __forceinline__ void cp16(uint32_t dst, const void* src, bool p) {
    asm volatile("cp.async.cg.shared.global [%0], [%1], 16, %2;"
                 :: "r"(dst), "l"(src), "r"(p ? 16 : 0));
}
__device__ __forceinline__ void cp_commit() {
    asm volatile("cp.async.commit_group;");
}
template <int N> __device__ __forceinline__ void cp_wait() {
    asm volatile("cp.async.wait_group %0;" :: "n"(N));
}
__device__ __forceinline__ void ldsm4(uint32_t r[4], uint32_t a) {
    asm volatile("ldmatrix.sync.aligned.m8n8.x4.shared.b16 {%0,%1,%2,%3}, [%4];"
                 : "=r"(r[0]), "=r"(r[1]), "=r"(r[2]), "=r"(r[3]) : "r"(a));
}
__device__ __forceinline__ uint32_t pack_bf2(__nv_bfloat16 a, __nv_bfloat16 b) {
    __nv_bfloat162 t{a, b};
    return *reinterpret_cast<uint32_t*>(&t);
}

// ---------------- fp32 -> bf16 hi/lo split (streaming) ----------------
__global__ void split_kernel(const float4* __restrict__ src,
                             uint2* __restrict__ hi, uint2* __restrict__ lo,
                             int n4)
{
    int i = blockIdx.x * blockDim.x + threadIdx.x;
    const int stride = gridDim.x * blockDim.x;
    for (; i < n4; i += stride) {
        float4 v = src[i];
        __nv_bfloat16 h0 = __float2bfloat16(v.x), h1 = __float2bfloat16(v.y);
        __nv_bfloat16 h2 = __float2bfloat16(v.z), h3 = __float2bfloat16(v.w);
        uint2 H, L;
        H.x = pack_bf2(h0, h1);
        H.y = pack_bf2(h2, h3);
        L.x = pack_bf2(__float2bfloat16(v.x - __bfloat162float(h0)),
                       __float2bfloat16(v.y - __bfloat162float(h1)));
        L.y = pack_bf2(__float2bfloat16(v.z - __bfloat162float(h2)),
                       __float2bfloat16(v.w - __bfloat162float(h3)));
        hi[i] = H;
        lo[i] = L;
    }
}

// ---------------------------------------------------------------------------
// C = relu(A @ W^T + bias), A:[M,K] (hi/lo bf16), W:[N,K] (hi/lo bf16).
// Output written as bf16 hi/lo pair. K%64==0, N%64==0, M bounds-checked.
// 256 threads (8 warps, 4x2 of 32x32 warp tiles), 2-stage cp.async pipeline.
// ---------------------------------------------------------------------------
__global__ __launch_bounds__(256, 2)
void gemm_bf16x3(const __nv_bfloat16* __restrict__ Ahi,
                 const __nv_bfloat16* __restrict__ Alo,
                 const __nv_bfloat16* __restrict__ Whi,
                 const __nv_bfloat16* __restrict__ Wlo,
                 const float* __restrict__ bias,
                 __nv_bfloat16* __restrict__ Chi,
                 __nv_bfloat16* __restrict__ Clo,
                 int M, int N, int K)
{
    extern __shared__ char smem[];
    const uint32_t sbase = (uint32_t)__cvta_generic_to_shared(smem);

    const int tid  = threadIdx.x;
    const int lane = tid & 31;
    const int wid  = tid >> 5;
    const int wm   = (wid & 3) * 32;
    const int wn   = (wid >> 2) * 32;
    const int bm   = blockIdx.y * BM;
    const int bn   = blockIdx.x * BN;

    // copy roles: 16B chunks; 8 chunks per 64-col row
    const int crow = tid >> 3;              // 0..31
    const int ccol = (tid & 7) * 8;         // bf16 elem col
    const int cchkB = (tid & 7) * 16;       // byte col

    // ldmatrix lane mapping
    const int lr8  = lane & 7;
    const int g    = lane >> 3;
    const int mrow = (g & 1) * 8;
    const int kcolB = (g >> 1) * 16;        // 8 bf16 = 16 bytes

    float acc[2][4][4];
    #pragma unroll
    for (int i = 0; i < 2; i++)
        #pragma unroll
        for (int j = 0; j < 4; j++)
            #pragma unroll
            for (int v = 0; v < 4; v++) acc[i][j][v] = 0.f;

    const int nT = K / BK;

    auto stage = [&](int s, int k0) {
        const uint32_t sa_hi = sbase + s * STAGE_B;
        const uint32_t sa_lo = sa_hi + A_TILE_B;
        const uint32_t sb_hi = sa_lo + A_TILE_B;
        const uint32_t sb_lo = sb_hi + B_TILE_B;
        #pragma unroll
        for (int i = 0; i < 4; i++) {
            const int r = crow + i * 32;
            const bool p = (bm + r) < M;
            const size_t go = (size_t)(bm + r) * K + k0 + ccol;
            cp16(sa_hi + r * LDA_B + cchkB, Ahi + go, p);
            cp16(sa_lo + r * LDA_B + cchkB, Alo + go, p);
        }
        #pragma unroll
        for (int i = 0; i < 2; i++) {
            const int r = crow + i * 32;
            const size_t go = (size_t)(bn + r) * K + k0 + ccol;
            cp16(sb_hi + r * LDA_B + cchkB, Whi + go, true);
            cp16(sb_lo + r * LDA_B + cchkB, Wlo + go, true);
        }
        cp_commit();
    };

    stage(0, 0);
    for (int kt = 0; kt < nT; kt++) {
        if (kt + 1 < nT) {
            stage((kt + 1) & 1, (kt + 1) * BK);
            cp_wait<1>();
        } else {
            cp_wait<0>();
        }
        __syncthreads();

        const uint32_t s0    = sbase + (kt & 1) * STAGE_B;
        const uint32_t sa_hi = s0;
        const uint32_t sa_lo = s0 + A_TILE_B;
        const uint32_t sb_hi = sa_lo + A_TILE_B;
        const uint32_t sb_lo = sb_hi + B_TILE_B;

        #pragma unroll
        for (int ks = 0; ks < BK; ks += 16) {
            uint32_t ah[2][4], al[2][4], bh[2][4], bl[2][4];
            #pragma unroll
            for (int mi = 0; mi < 2; mi++) {
                const uint32_t off =
                    (uint32_t)(wm + mi * 16 + mrow + lr8) * LDA_B + ks * 2 + kcolB;
                ldsm4(ah[mi], sa_hi + off);
                ldsm4(al[mi], sa_lo + off);
            }
            #pragma unroll
            for (int p = 0; p < 2; p++) {
                const uint32_t off =
                    (uint32_t)(wn + p * 16 + mrow + lr8) * LDA_B + ks * 2 + kcolB;
                ldsm4(bh[p], sb_hi + off);
                ldsm4(bl[p], sb_lo + off);
            }
            // bh[p] = { b[2p]k0, b[2p+1]k0, b[2p]k8, b[2p+1]k8 }
            #pragma unroll
            for (int mi = 0; mi < 2; mi++)
                #pragma unroll
                for (int ni = 0; ni < 4; ni++) {
                    const int p = ni >> 1, q = ni & 1;
                    mma_bf16(acc[mi][ni], ah[mi], bh[p][q], bh[p][q + 2]);
                    mma_bf16(acc[mi][ni], ah[mi], bl[p][q], bl[p][q + 2]);
                    mma_bf16(acc[mi][ni], al[mi], bh[p][q], bh[p][q + 2]);
                }
        }
        __syncthreads();
    }

    // ---- epilogue: bias + relu, split into hi/lo bf16 ----
    const int lq = (lane & 3) * 2;
    const int lr = lane >> 2;
    #pragma unroll
    for (int mi = 0; mi < 2; mi++) {
        #pragma unroll
        for (int ni = 0; ni < 4; ni++) {
            const int m0 = bm + wm + mi * 16 + lr;
            const int n  = bn + wn + ni * 8 + lq;
            const float bv0 = bias[n], bv1 = bias[n + 1];
            #pragma unroll
            for (int h = 0; h < 2; h++) {
                const int m = m0 + h * 8;
                if (m < M) {
                    float x0 = fmaxf(acc[mi][ni][2 * h]     + bv0, 0.f);
                    float x1 = fmaxf(acc[mi][ni][2 * h + 1] + bv1, 0.f);
                    __nv_bfloat16 h0 = __float2bfloat16(x0);
                    __nv_bfloat16 h1 = __float2bfloat16(x1);
                    __nv_bfloat16 l0 = __float2bfloat16(x0 - __bfloat162float(h0));
                    __nv_bfloat16 l1 = __float2bfloat16(x1 - __bfloat162float(h1));
                    *reinterpret_cast<uint32_t*>(Chi + (size_t)m * N + n) = pack_bf2(h0, h1);
                    *reinterpret_cast<uint32_t*>(Clo + (size_t)m * N + n) = pack_bf2(l0, l1);
                }
            }
        }
    }
}

// Root projection: out[c] = sum_k (hi[k]+lo[k]) * Wp[c*512+k] + bp[c]
__global__ void proj_kernel(const __nv_bfloat16* __restrict__ hhi,
                            const __nv_bfloat16* __restrict__ hlo,
                            const float* __restrict__ Wp,
                            const float* __restrict__ bp,
                            float* __restrict__ out)
{
    const int w    = threadIdx.x >> 5;
    const int lane = threadIdx.x & 31;
    float s = 0.f;
    for (int k = lane; k < 512; k += 32) {
        const float hv = __bfloat162float(hhi[k]) + __bfloat162float(hlo[k]);
        s = fmaf(hv, Wp[w * 512 + k], s);
    }
    #pragma unroll
    for (int o = 16; o > 0; o >>= 1)
        s += __shfl_xor_sync(0xffffffffu, s, o);
    if (lane == 0) out[w] = s + bp[w];
}

extern "C" void kernel_launch(void* const* d_in, const int* in_sizes, int n_in,
                              void* d_out, int out_size)
{
    const float* leaf  = (const float*)d_in[0];   // [8192, 4096]
    const float* Wemb  = (const float*)d_in[1];   // [512, 4096]
    const float* bemb  = (const float*)d_in[2];   // [512]
    const float* Wcomb = (const float*)d_in[3];   // [512, 1024]
    const float* bcomb = (const float*)d_in[4];   // [512]
    const float* Wproj = (const float*)d_in[5];   // [2, 512]
    const float* bproj = (const float*)d_in[6];   // [2]
    float* out = (float*)d_out;

    __nv_bfloat16 *leaf_hi, *leaf_lo, *We_hi, *We_lo, *Wc_hi, *Wc_lo;
    __nv_bfloat16 *hA, *lA, *hB, *lB;
    cudaGetSymbolAddress((void**)&leaf_hi, g_leaf_hi);
    cudaGetSymbolAddress((void**)&leaf_lo, g_leaf_lo);
    cudaGetSymbolAddress((void**)&We_hi, g_We_hi);
    cudaGetSymbolAddress((void**)&We_lo, g_We_lo);
    cudaGetSymbolAddress((void**)&Wc_hi, g_Wc_hi);
    cudaGetSymbolAddress((void**)&Wc_lo, g_Wc_lo);
    cudaGetSymbolAddress((void**)&hA, g_hA);
    cudaGetSymbolAddress((void**)&lA, g_lA);
    cudaGetSymbolAddress((void**)&hB, g_hB);
    cudaGetSymbolAddress((void**)&lB, g_lB);

    cudaFuncSetAttribute(gemm_bf16x3,
                         cudaFuncAttributeMaxDynamicSharedMemorySize, SMEM_TOTAL);

    // ---- pre-split fp32 inputs into bf16 hi/lo ----
    {
        const int n4_leaf = 8192 * 4096 / 4;
        split_kernel<<<4096, 256>>>((const float4*)leaf,
                                    (uint2*)leaf_hi, (uint2*)leaf_lo, n4_leaf);
        const int n4_we = 512 * 4096 / 4;
        split_kernel<<<1024, 256>>>((const float4*)Wemb,
                                    (uint2*)We_hi, (uint2*)We_lo, n4_we);
        const int n4_wc = 512 * 1024 / 4;
        split_kernel<<<512, 256>>>((const float4*)Wcomb,
                                   (uint2*)Wc_hi, (uint2*)Wc_lo, n4_wc);
    }

    // ---- leaf embedding: [8192,4096] @ [512,4096]^T -> hA/lA ----
    {
        dim3 grid(512 / BN, 8192 / BM);
        gemm_bf16x3<<<grid, 256, SMEM_TOTAL>>>(leaf_hi, leaf_lo, We_hi, We_lo,
                                               bemb, hA, lA, 8192, 512, 4096);
    }

    // ---- 13 combine levels: [rows,512] viewed as [rows/2,1024] ----
    __nv_bfloat16 *cur_h = hA, *cur_l = lA, *nxt_h = hB, *nxt_l = lB;
    int rows = 8192;
    while (rows > 1) {
        const int m = rows / 2;
        dim3 grid(512 / BN, (m + BM - 1) / BM);
        gemm_bf16x3<<<grid, 256, SMEM_TOTAL>>>(cur_h, cur_l, Wc_hi, Wc_lo,
                                               bcomb, nxt_h, nxt_l, m, 512, 1024);
        __nv_bfloat16* t;
        t = cur_h; cur_h = nxt_h; nxt_h = t;
        t = cur_l; cur_l = nxt_l; nxt_l = t;
        rows = m;
    }

    proj_kernel<<<1, 64>>>(cur_h, cur_l, Wproj, bproj, out);
}

// round 5
// speedup vs baseline: 3.4646x; 1.0499x over previous
#include <cuda_runtime.h>
#include <cuda_bf16.h>
#include <cstdint>

// Tree-RNN, bf16x3-split GEMMs on mma.sync tensor cores.
// 4-stage cp.async ring, prefetch distance 2, ONE __syncthreads per k-tile.
// hi/lo interleaved in 128-byte smem rows with XOR swizzle (conflict-free
// ldmatrix + cp.async), BK=32.

#define BM 128
#define BN 64
#define BK 32
#define A_T (BM * 128)              // 16384 B (row = hi 64B | lo 64B)
#define B_T (BN * 128)              // 8192 B
#define STAGE_B (A_T + B_T)         // 24576
#define NSTAGE 4
#define SMEM_TOTAL (NSTAGE * STAGE_B)   // 98304

// ---------------- device scratch (no allocation allowed) ----------------
__device__ __nv_bfloat16 g_leaf_hi[8192ull * 4096];
__device__ __nv_bfloat16 g_leaf_lo[8192ull * 4096];
__device__ __nv_bfloat16 g_We_hi[512 * 4096];
__device__ __nv_bfloat16 g_We_lo[512 * 4096];
__device__ __nv_bfloat16 g_Wc_hi[512 * 1024];
__device__ __nv_bfloat16 g_Wc_lo[512 * 1024];
__device__ __nv_bfloat16 g_hA[8192 * 512], g_lA[8192 * 512];
__device__ __nv_bfloat16 g_hB[4096 * 512], g_lB[4096 * 512];

// ---------------- PTX helpers ----------------
__device__ __forceinline__ void mma_bf16(float c[4], const uint32_t a[4],
                                         const uint32_t b0, const uint32_t b1) {
    asm volatile(
        "mma.sync.aligned.m16n8k16.row.col.f32.bf16.bf16.f32 "
        "{%0,%1,%2,%3}, {%4,%5,%6,%7}, {%8,%9}, {%0,%1,%2,%3};\n"
        : "+f"(c[0]), "+f"(c[1]), "+f"(c[2]), "+f"(c[3])
        : "r"(a[0]), "r"(a[1]), "r"(a[2]), "r"(a[3]), "r"(b0), "r"(b1));
}
__device__ __forceinline__ void cp16(uint32_t dst, const void* src, bool p) {
    asm volatile("cp.async.cg.shared.global [%0], [%1], 16, %2;"
                 :: "r"(dst), "l"(src), "r"(p ? 16 : 0));
}
__device__ __forceinline__ void cp_commit() {
    asm volatile("cp.async.commit_group;");
}
template <int N> __device__ __forceinline__ void cp_wait() {
    asm volatile("cp.async.wait_group %0;" :: "n"(N));
}
__device__ __forceinline__ void ldsm4(uint32_t r[4], uint32_t a) {
    asm volatile("ldmatrix.sync.aligned.m8n8.x4.shared.b16 {%0,%1,%2,%3}, [%4];"
                 : "=r"(r[0]), "=r"(r[1]), "=r"(r[2]), "=r"(r[3]) : "r"(a));
}
__device__ __forceinline__ uint32_t pack_bf2(__nv_bfloat16 a, __nv_bfloat16 b) {
    __nv_bfloat162 t{a, b};
    return *reinterpret_cast<uint32_t*>(&t);
}

// ---------------- fp32 -> bf16 hi/lo split (streaming) ----------------
__global__ void split_kernel(const float4* __restrict__ src,
                             uint2* __restrict__ hi, uint2* __restrict__ lo,
                             int n4)
{
    int i = blockIdx.x * blockDim.x + threadIdx.x;
    const int stride = gridDim.x * blockDim.x;
    for (; i < n4; i += stride) {
        float4 v = src[i];
        __nv_bfloat16 h0 = __float2bfloat16(v.x), h1 = __float2bfloat16(v.y);
        __nv_bfloat16 h2 = __float2bfloat16(v.z), h3 = __float2bfloat16(v.w);
        uint2 H, L;
        H.x = pack_bf2(h0, h1);
        H.y = pack_bf2(h2, h3);
        L.x = pack_bf2(__float2bfloat16(v.x - __bfloat162float(h0)),
                       __float2bfloat16(v.y - __bfloat162float(h1)));
        L.y = pack_bf2(__float2bfloat16(v.z - __bfloat162float(h2)),
                       __float2bfloat16(v.w - __bfloat162float(h3)));
        hi[i] = H;
        lo[i] = L;
    }
}

// ---------------------------------------------------------------------------
// C = relu(A @ W^T + bias): A [M,K] hi/lo bf16, W [N,K] hi/lo bf16,
// C emitted as hi/lo bf16. K%32==0, N%64==0, M bounds-checked.
// 256 threads = 8 warps (4 M x 2 N of 32x32 warp tiles).
// ---------------------------------------------------------------------------
__global__ __launch_bounds__(256, 2)
void gemm_bf16x3(const __nv_bfloat16* __restrict__ Ahi,
                 const __nv_bfloat16* __restrict__ Alo,
                 const __nv_bfloat16* __restrict__ Whi,
                 const __nv_bfloat16* __restrict__ Wlo,
                 const float* __restrict__ bias,
                 __nv_bfloat16* __restrict__ Chi,
                 __nv_bfloat16* __restrict__ Clo,
                 int M, int N, int K)
{
    extern __shared__ __align__(1024) char smem[];
    const uint32_t sbase = (uint32_t)__cvta_generic_to_shared(smem);

    const int tid  = threadIdx.x;
    const int lane = tid & 31;
    const int wid  = tid >> 5;
    const int wm   = (wid & 3) * 32;
    const int wn   = (wid >> 2) * 32;
    const int bm   = blockIdx.y * BM;
    const int bn   = blockIdx.x * BN;

    // ldmatrix lane mapping (same as verified R2 kernel)
    const int lr8   = lane & 7;
    const int g     = lane >> 3;
    const int mrow  = (g & 1) * 8;
    const int kcolB = (g >> 1) * 16;

    // Precompute per-thread swizzled row bases for frag loads.
    // raw = rowB + colB, colB < 128 -> swizzle mask depends only on rowB.
    // addr = stagebase + rowB + (colB ^ xm), xm = (rowB>>3)&0x70.
    uint32_t aRow[2], aXm[2], bRow[2], bXm[2];
    #pragma unroll
    for (int mi = 0; mi < 2; mi++) {
        const uint32_t rB = (uint32_t)(wm + mi * 16 + mrow + lr8) * 128;
        aRow[mi] = rB;
        aXm[mi]  = (rB >> 3) & 0x70;
    }
    #pragma unroll
    for (int p = 0; p < 2; p++) {
        const uint32_t rB = (uint32_t)(wn + p * 16 + mrow + lr8) * 128;
        bRow[p] = A_T + rB;          // B region follows A within a stage
        bXm[p]  = (rB >> 3) & 0x70;
    }

    float acc[2][4][4];
    #pragma unroll
    for (int i = 0; i < 2; i++)
        #pragma unroll
        for (int j = 0; j < 4; j++)
            #pragma unroll
            for (int v = 0; v < 4; v++) acc[i][j][v] = 0.f;

    const int nT = K / BK;

    // staging: chunk linear ids; A has 1024 16B chunks (4/thread),
    // B has 512 (2/thread). chunk: row = lin>>3, c = lin&7 (c<4 hi, c>=4 lo).
    auto stage = [&](int lt) {
        const uint32_t sb = sbase + (lt & (NSTAGE - 1)) * STAGE_B;
        const int k0 = lt * BK;
        #pragma unroll
        for (int i = 0; i < 4; i++) {
            const int lin = tid + i * 256;
            const int r = lin >> 3;
            const int c = lin & 7;
            const uint32_t off = (uint32_t)r * 128 + (uint32_t)c * 16;
            const uint32_t sw = off ^ ((off >> 3) & 0x70);
            const bool pa = (bm + r) < M;
            const __nv_bfloat16* src = (c < 4) ? Ahi : Alo;
            cp16(sb + sw, src + (size_t)(bm + r) * K + k0 + (c & 3) * 8, pa);
        }
        #pragma unroll
        for (int i = 0; i < 2; i++) {
            const int lin = tid + i * 256;
            const int r = lin >> 3;
            const int c = lin & 7;
            const uint32_t off = (uint32_t)r * 128 + (uint32_t)c * 16;
            const uint32_t sw = off ^ ((off >> 3) & 0x70);
            const __nv_bfloat16* src = (c < 4) ? Whi : Wlo;
            cp16(sb + A_T + sw, src + (size_t)(bn + r) * K + k0 + (c & 3) * 8, true);
        }
        cp_commit();
    };

    // prologue: prefetch 2 tiles
    stage(0);
    stage(1);

    for (int kt = 0; kt < nT; kt++) {
        if (kt + 1 < nT) cp_wait<1>();   // tile kt complete (newest 1 pending)
        else             cp_wait<0>();
        __syncthreads();                  // all chunks of tile kt visible;
                                          // all warps done with tile kt-1
        if (kt + 2 < nT) stage(kt + 2);   // buffer (kt+2)%4 last read @ kt-2

        const uint32_t s0 = sbase + (kt & (NSTAGE - 1)) * STAGE_B;

        #pragma unroll
        for (int ks = 0; ks < BK; ks += 16) {
            const uint32_t colH = (uint32_t)(ks * 2) + kcolB;       // hi region
            const uint32_t colL = 64u + (uint32_t)(ks * 2) + kcolB; // lo region
            uint32_t ah[2][4], al[2][4], bh[2][4], bl[2][4];
            #pragma unroll
            for (int mi = 0; mi < 2; mi++) {
                ldsm4(ah[mi], s0 + aRow[mi] + (colH ^ aXm[mi]));
                ldsm4(al[mi], s0 + aRow[mi] + (colL ^ aXm[mi]));
            }
            #pragma unroll
            for (int p = 0; p < 2; p++) {
                ldsm4(bh[p], s0 + bRow[p] + (colH ^ bXm[p]));
                ldsm4(bl[p], s0 + bRow[p] + (colL ^ bXm[p]));
            }
            #pragma unroll
            for (int mi = 0; mi < 2; mi++)
                #pragma unroll
                for (int ni = 0; ni < 4; ni++) {
                    const int p = ni >> 1, q = ni & 1;
                    mma_bf16(acc[mi][ni], ah[mi], bh[p][q], bh[p][q + 2]);
                    mma_bf16(acc[mi][ni], ah[mi], bl[p][q], bl[p][q + 2]);
                    mma_bf16(acc[mi][ni], al[mi], bh[p][q], bh[p][q + 2]);
                }
        }
    }

    // ---- epilogue: bias + relu, split into hi/lo bf16 ----
    const int lq = (lane & 3) * 2;
    const int lr = lane >> 2;
    #pragma unroll
    for (int mi = 0; mi < 2; mi++) {
        #pragma unroll
        for (int ni = 0; ni < 4; ni++) {
            const int m0 = bm + wm + mi * 16 + lr;
            const int n  = bn + wn + ni * 8 + lq;
            const float bv0 = __ldg(bias + n), bv1 = __ldg(bias + n + 1);
            #pragma unroll
            for (int h = 0; h < 2; h++) {
                const int m = m0 + h * 8;
                if (m < M) {
                    float x0 = fmaxf(acc[mi][ni][2 * h]     + bv0, 0.f);
                    float x1 = fmaxf(acc[mi][ni][2 * h + 1] + bv1, 0.f);
                    __nv_bfloat16 h0 = __float2bfloat16(x0);
                    __nv_bfloat16 h1 = __float2bfloat16(x1);
                    __nv_bfloat16 l0 = __float2bfloat16(x0 - __bfloat162float(h0));
                    __nv_bfloat16 l1 = __float2bfloat16(x1 - __bfloat162float(h1));
                    *reinterpret_cast<uint32_t*>(Chi + (size_t)m * N + n) = pack_bf2(h0, h1);
                    *reinterpret_cast<uint32_t*>(Clo + (size_t)m * N + n) = pack_bf2(l0, l1);
                }
            }
        }
    }
}

// Root projection: out[c] = sum_k (hi[k]+lo[k]) * Wp[c*512+k] + bp[c]
__global__ void proj_kernel(const __nv_bfloat16* __restrict__ hhi,
                            const __nv_bfloat16* __restrict__ hlo,
                            const float* __restrict__ Wp,
                            const float* __restrict__ bp,
                            float* __restrict__ out)
{
    const int w    = threadIdx.x >> 5;
    const int lane = threadIdx.x & 31;
    float s = 0.f;
    for (int k = lane; k < 512; k += 32) {
        const float hv = __bfloat162float(hhi[k]) + __bfloat162float(hlo[k]);
        s = fmaf(hv, Wp[w * 512 + k], s);
    }
    #pragma unroll
    for (int o = 16; o > 0; o >>= 1)
        s += __shfl_xor_sync(0xffffffffu, s, o);
    if (lane == 0) out[w] = s + bp[w];
}

extern "C" void kernel_launch(void* const* d_in, const int* in_sizes, int n_in,
                              void* d_out, int out_size)
{
    const float* leaf  = (const float*)d_in[0];   // [8192, 4096]
    const float* Wemb  = (const float*)d_in[1];   // [512, 4096]
    const float* bemb  = (const float*)d_in[2];   // [512]
    const float* Wcomb = (const float*)d_in[3];   // [512, 1024]
    const float* bcomb = (const float*)d_in[4];   // [512]
    const float* Wproj = (const float*)d_in[5];   // [2, 512]
    const float* bproj = (const float*)d_in[6];   // [2]
    float* out = (float*)d_out;

    __nv_bfloat16 *leaf_hi, *leaf_lo, *We_hi, *We_lo, *Wc_hi, *Wc_lo;
    __nv_bfloat16 *hA, *lA, *hB, *lB;
    cudaGetSymbolAddress((void**)&leaf_hi, g_leaf_hi);
    cudaGetSymbolAddress((void**)&leaf_lo, g_leaf_lo);
    cudaGetSymbolAddress((void**)&We_hi, g_We_hi);
    cudaGetSymbolAddress((void**)&We_lo, g_We_lo);
    cudaGetSymbolAddress((void**)&Wc_hi, g_Wc_hi);
    cudaGetSymbolAddress((void**)&Wc_lo, g_Wc_lo);
    cudaGetSymbolAddress((void**)&hA, g_hA);
    cudaGetSymbolAddress((void**)&lA, g_lA);
    cudaGetSymbolAddress((void**)&hB, g_hB);
    cudaGetSymbolAddress((void**)&lB, g_lB);

    cudaFuncSetAttribute(gemm_bf16x3,
                         cudaFuncAttributeMaxDynamicSharedMemorySize, SMEM_TOTAL);

    // ---- pre-split fp32 inputs into bf16 hi/lo ----
    split_kernel<<<4096, 256>>>((const float4*)leaf,
                                (uint2*)leaf_hi, (uint2*)leaf_lo, 8192 * 4096 / 4);
    split_kernel<<<1024, 256>>>((const float4*)Wemb,
                                (uint2*)We_hi, (uint2*)We_lo, 512 * 4096 / 4);
    split_kernel<<<512, 256>>>((const float4*)Wcomb,
                               (uint2*)Wc_hi, (uint2*)Wc_lo, 512 * 1024 / 4);

    // ---- leaf embedding: [8192,4096] @ [512,4096]^T -> hA/lA ----
    {
        dim3 grid(512 / BN, 8192 / BM);
        gemm_bf16x3<<<grid, 256, SMEM_TOTAL>>>(leaf_hi, leaf_lo, We_hi, We_lo,
                                               bemb, hA, lA, 8192, 512, 4096);
    }

    // ---- 13 combine levels: [rows,512] viewed as [rows/2,1024] ----
    __nv_bfloat16 *cur_h = hA, *cur_l = lA, *nxt_h = hB, *nxt_l = lB;
    int rows = 8192;
    while (rows > 1) {
        const int m = rows / 2;
        dim3 grid(512 / BN, (m + BM - 1) / BM);
        gemm_bf16x3<<<grid, 256, SMEM_TOTAL>>>(cur_h, cur_l, Wc_hi, Wc_lo,
                                               bcomb, nxt_h, nxt_l, m, 512, 1024);
        __nv_bfloat16* t;
        t = cur_h; cur_h = nxt_h; nxt_h = t;
        t = cur_l; cur_l = nxt_l; nxt_l = t;
        rows = m;
    }

    proj_kernel<<<1, 64>>>(cur_h, cur_l, Wproj, bproj, out);
}